// round 10
// baseline (speedup 1.0000x reference)
#include <cuda_runtime.h>
#include <cstdint>

// GlobalPoolDistance: patch-RBF MMD, single fused persistent kernel (R10).
// FP8 (e4m3) mma.sync m16n8k32 computes the exp2 argument directly:
//   A row i = [C2*a_0..C2*a_26, 1, -u_i, 0..]   (u = ||a||^2 * log2e/SIG2)
//   B row j = [b_0..b_26,      -v_j, 1, 0..]
//   acc(i,j) = C2*<a,b> - u - v ~= -log2e*||a-b||^2/SIG2 ; K = exp2(acc).
// fp8 quantization error (|arg err| <~ 30) is irrelevant: off-diag args are
// ~ -267 (vs threshold -30, margin ~200); diagonals are POSITIONALLY
// replaced by exact 1.0 and straddle tiles force the epilogue, so no value
// depends on fp8 accuracy.  Dropped terms bound as in R7 (rel <= ~1e-5).
// K=32 in ONE mma -> 8 QMMA per warp-tile (halves the R9 instruction floor).

#define TILE 128
#define BTILE 64
#define NPATCH 3844
#define NTILES 31
#define NROWS (NTILES * TILE)                     // 3968
#define BATCH 8
#define ROW_U4 2                                  // 32 B per fp8 row
#define STAGE_U4 (4 * BATCH * NROWS * ROW_U4)     // 4 MB
#define XY_CHUNKS 1984
#define SYM_CHUNKS_PER 136
#define CHUNKS (XY_CHUNKS + 16 * SYM_CHUNKS_PER)  // 4160
#define WORKERS 444                               // 148 SMs x 3 CTAs
#define STAGE_TASKS (2 * BATCH * NROWS)           // 63488

__device__ uint4 g_stage[STAGE_U4];
__device__ float g_partials[WORKERS];
__device__ unsigned int g_bar1;
__device__ unsigned int g_ticket;
__device__ unsigned int g_done;

__device__ __forceinline__ uint32_t smem_to_u32(const void* p) {
    uint32_t a;
    asm("{ .reg .u64 t; cvta.to.shared.u64 t, %1; cvt.u32.u64 %0, t; }"
        : "=r"(a) : "l"(p));
    return a;
}
__device__ __forceinline__ void cp_async16(uint32_t smem, const void* gptr) {
    asm volatile("cp.async.cg.shared.global [%0], [%1], 16;"
                 :: "r"(smem), "l"(gptr) : "memory");
}
#define CP_COMMIT() asm volatile("cp.async.commit_group;" ::: "memory")
#define CP_WAIT0()  asm volatile("cp.async.wait_group 0;" ::: "memory")

__device__ __forceinline__ void ldsm_x4(uint32_t& r0, uint32_t& r1,
                                        uint32_t& r2, uint32_t& r3, uint32_t a) {
    asm volatile("ldmatrix.sync.aligned.m8n8.x4.shared.b16 {%0,%1,%2,%3}, [%4];"
                 : "=r"(r0), "=r"(r1), "=r"(r2), "=r"(r3) : "r"(a));
}
// fp8 e4m3 MMA: D[16x8] += A[16x32] * B[8x32]^T, one instruction.
__device__ __forceinline__ void mma_fp8(float* d, const uint32_t* a,
                                        uint32_t b0, uint32_t b1) {
    asm volatile("mma.sync.aligned.m16n8k32.row.col.f32.e4m3.e4m3.f32 "
                 "{%0,%1,%2,%3}, {%4,%5,%6,%7}, {%8,%9}, {%0,%1,%2,%3};"
                 : "+f"(d[0]), "+f"(d[1]), "+f"(d[2]), "+f"(d[3])
                 : "r"(a[0]), "r"(a[1]), "r"(a[2]), "r"(a[3]), "r"(b0), "r"(b1));
}
// pack 4 floats into 4 e4m3 bytes (little-endian: v0 -> byte 0)
__device__ __forceinline__ uint32_t fp8x4(float v0, float v1, float v2, float v3) {
    uint16_t p0, p1;
    asm("cvt.rn.satfinite.e4m3x2.f32 %0, %1, %2;" : "=h"(p0) : "f"(v1), "f"(v0));
    asm("cvt.rn.satfinite.e4m3x2.f32 %0, %1, %2;" : "=h"(p1) : "f"(v3), "f"(v2));
    return (uint32_t)p0 | ((uint32_t)p1 << 16);
}

struct __align__(1024) Smem {
    uint4 A[256];          // 4 KB A tile (128 rows x 32 B)
    uint4 B[4][128];       // 4-slot B ring, 2 KB each (64 rows x 32 B)
    float red[8];
    unsigned int ticket;
    unsigned int lastflag;
};

__global__ void __launch_bounds__(256, 3)
mmd_fused(const float* __restrict__ x, const float* __restrict__ y,
          float* __restrict__ out) {
    __shared__ Smem sm;
    const int tid = threadIdx.x;
    const int wid = tid >> 5;
    const int lane = tid & 31;

    const float K1f = 4.9479492581208223f;        // log2e / 0.2916
    const float C2f = 9.8958985162416446f;        // 2*log2e / 0.2916

    // ================= Phase 1: stage fp8 operand rows =================
    {
        int gtid = blockIdx.x * 256 + tid;
        if (gtid < STAGE_TASKS) {
            int n = gtid % NROWS;
            int t2 = gtid / NROWS;
            int b = t2 & 7;
            int img = t2 >> 3;
            const float* im = img ? y : x;

            float rv[27];
            float u = 0.0f;
            bool valid = (n < NPATCH);
            if (valid) {
                int i = n / 62;
                int j = n - i * 62;
                const float* p = im + b * 12288 + (i << 6) + j;
                float sq = 0.0f;
                #pragma unroll
                for (int c = 0; c < 3; c++)
                    #pragma unroll
                    for (int rr = 0; rr < 3; rr++)
                        #pragma unroll
                        for (int ss = 0; ss < 3; ss++) {
                            float v = p[c * 4096 + (rr << 6) + ss];
                            sq = fmaf(v, v, sq);
                            rv[c * 9 + rr * 3 + ss] = v;
                        }
                u = sq * K1f;
            } else {
                #pragma unroll
                for (int k = 0; k < 27; k++) rv[k] = 0.0f;
            }
            uint32_t sw = (uint32_t)(n >> 2) & 1u;   // 32B-row chunk swizzle

            #pragma unroll
            for (int form = 0; form < 2; form++) {
                float rowv[32];
                #pragma unroll
                for (int k = 0; k < 27; k++)
                    rowv[k] = form ? rv[k] : (C2f * rv[k]);
                float nu = valid ? -u : -1e30f;      // satfinite -> -448 for pads
                if (form) { rowv[27] = nu;   rowv[28] = 1.0f; }
                else      { rowv[27] = 1.0f; rowv[28] = nu;   }
                rowv[29] = rowv[30] = rowv[31] = 0.0f;
                uint32_t wds[8];
                #pragma unroll
                for (int q = 0; q < 8; q++)
                    wds[q] = fp8x4(rowv[4*q], rowv[4*q+1], rowv[4*q+2], rowv[4*q+3]);
                int ver = form * 2 + img;
                int base = ((ver * BATCH + b) * NROWS + n) * ROW_U4;
                #pragma unroll
                for (int c = 0; c < 2; c++)
                    g_stage[base + (c ^ sw)] =
                        make_uint4(wds[4*c], wds[4*c+1], wds[4*c+2], wds[4*c+3]);
            }
        }
        __threadfence();
        __syncthreads();
        if (tid == 0) {
            atomicAdd(&g_bar1, 1u);
            unsigned int v;
            do {
                asm volatile("ld.acquire.gpu.global.u32 %0, [%1];"
                             : "=r"(v) : "l"(&g_bar1));
                if (v >= WORKERS) break;
                __nanosleep(64);
            } while (true);
        }
        __syncthreads();
        __threadfence();
    }

    // ================= Phase 2: persistent tile loop =================
    const int mg = wid & 3;          // A rows mg*32..+31
    const int ng = wid >> 2;         // B rows ng*32..+31
    const uint32_t a_base = smem_to_u32(sm.A);
    const uint32_t b_ring = smem_to_u32(sm.B);    // 4 slots x 2048 B

    // ldmatrix addresses, 32 B rows, chunk swizzle c ^ ((row>>2)&1)
    uint32_t offA[2];
    #pragma unroll
    for (int mt = 0; mt < 2; mt++) {
        int rowA = mg * 32 + mt * 16 + (lane & 15);
        int ch = lane >> 4;
        int phys = ch ^ ((rowA >> 2) & 1);
        offA[mt] = (uint32_t)(rowA * 32 + phys * 16);
    }
    uint32_t offB;
    {
        int rloc = (lane & 7) + ((lane >> 4) << 3);
        int rowB = ng * 32 + rloc;
        int ch = (lane >> 3) & 1;
        int phys = ch ^ ((rowB >> 2) & 1);
        offB = (uint32_t)(rowB * 32 + phys * 16);
    }

    float s = 0.0f;
    uint32_t af[2][4];               // A fragments, K=32 in one fragment

    auto compute_tile = [&](int slot, int ti, int tj, bool sym) {
        const uint32_t bb = b_ring + (uint32_t)(slot * 2048);
        float acc[2][4][4];
        #pragma unroll
        for (int mt = 0; mt < 2; mt++)
            #pragma unroll
            for (int nt = 0; nt < 4; nt++)
                #pragma unroll
                for (int r = 0; r < 4; r++) acc[mt][nt][r] = 0.0f;

        #pragma unroll
        for (int p = 0; p < 2; p++) {            // 2 ldmatrix = 4 n-tiles
            uint32_t b0, b1, b2, b3;
            ldsm_x4(b0, b1, b2, b3, bb + offB + (uint32_t)(p * 512));
            mma_fp8(acc[0][2*p],   af[0], b0, b1);
            mma_fp8(acc[0][2*p+1], af[0], b2, b3);
            mma_fp8(acc[1][2*p],   af[1], b0, b1);
            mma_fp8(acc[1][2*p+1], af[1], b2, b3);
        }

        bool diagTile = sym && ((tj >> 1) == ti);

        float t8[8];
        #pragma unroll
        for (int mt = 0; mt < 2; mt++)
            #pragma unroll
            for (int nt = 0; nt < 4; nt++)
                t8[mt * 4 + nt] = fmaxf(fmaxf(acc[mt][nt][0], acc[mt][nt][1]),
                                        fmaxf(acc[mt][nt][2], acc[mt][nt][3]));
        #pragma unroll
        for (int st = 4; st > 0; st >>= 1)
            #pragma unroll
            for (int i2 = 0; i2 < 4; i2++)
                if (i2 < st) t8[i2] = fmaxf(t8[i2], t8[i2 + st]);

        // force epilogue on straddle tiles (diag must never be dropped)
        if (diagTile || __any_sync(0xffffffffu, t8[0] > -30.0f)) {
            float w = sym ? ((tj < 2 * ti) ? 2.0f : 1.0f) : -2.0f;
            int rbase = mg * 32 + (lane >> 2);
            int cbase = ng * 32 + ((lane & 3) << 1);
            int dshift = (tj & 1) << 6;
            float ts = 0.0f;
            #pragma unroll
            for (int mt = 0; mt < 2; mt++)
                #pragma unroll
                for (int nt = 0; nt < 4; nt++)
                    #pragma unroll
                    for (int r = 0; r < 4; r++) {
                        int rl = rbase + mt * 16 + ((r >> 1) << 3);
                        int cl = cbase + nt * 8 + (r & 1);
                        bool isd = diagTile && (rl == dshift + cl) &&
                                   (ti * TILE + rl < NPATCH);
                        float e;
                        asm("ex2.approx.ftz.f32 %0, %1;" : "=f"(e)
                            : "f"(acc[mt][nt][r]));
                        ts += isd ? 1.0f : e;
                    }
            s = fmaf(w, ts, s);
        }
    };

    for (;;) {
        __syncthreads();
        if (tid == 0) sm.ticket = atomicAdd(&g_ticket, 1u);
        __syncthreads();
        unsigned int c = sm.ticket;
        if (c >= CHUNKS) break;

        // ---- decode 8-tile chunk (tiles 128 rows x 64 cols) ----
        int ti, tj0, len, verA, verB, b;
        bool sym;
        if (c < XY_CHUNKS) {
            int seg = c >> 3, q = c & 7;
            b = seg / 31; ti = seg - b * 31;
            tj0 = q * 8; len = (q < 7) ? 8 : 6;
            sym = false; verA = 0; verB = 3;
        } else {
            int d = (int)c - XY_CHUNKS;
            int g = d / SYM_CHUNKS_PER;
            int r = d - g * SYM_CHUNKS_PER;
            int kind = g >> 3; b = g & 7;
            int i = 0;
            for (;;) {
                int cpr = (2 * i + 9) >> 3;
                if (r < cpr) break;
                r -= cpr; i++;
            }
            ti = i;
            tj0 = r * 8;
            len = min(8, 2 * i + 2 - tj0);
            sym = true; verA = kind; verB = 2 + kind;
        }

        const uint4* bbase = g_stage + ((verB * BATCH + b) * NROWS) * ROW_U4;

        // ---- prologue: A (4 KB, 1 cp/thread) + first B pair ----
        {
            const uint4* asrc = g_stage + ((verA * BATCH + b) * NROWS + ti * TILE) * ROW_U4;
            cp_async16(a_base + (uint32_t)(tid * 16), asrc + tid);
            if (tid < 128) {
                const uint4* b0src = bbase + (tj0 * BTILE) * ROW_U4;
                cp_async16(b_ring + (uint32_t)(tid * 16), b0src + tid);
                if (len > 1) {
                    const uint4* b1src = bbase + ((tj0 + 1) * BTILE) * ROW_U4;
                    cp_async16(b_ring + (uint32_t)(2048 + tid * 16), b1src + tid);
                }
            }
            CP_COMMIT();
        }

        bool afload = false;
        for (int jp = 0; jp < len; jp += 2) {
            CP_WAIT0();
            __syncthreads();
            int pg = (jp >> 1) & 1;
            if (jp + 2 < len) {
                int og = pg ^ 1;
                uint32_t nb = b_ring + (uint32_t)(og * 2 * 2048);
                if (tid < 128) {
                    const uint4* bs = bbase + ((tj0 + jp + 2) * BTILE) * ROW_U4;
                    cp_async16(nb + (uint32_t)(tid * 16), bs + tid);
                    if (jp + 3 < len) {
                        const uint4* bs2 = bbase + ((tj0 + jp + 3) * BTILE) * ROW_U4;
                        cp_async16(nb + (uint32_t)(2048 + tid * 16), bs2 + tid);
                    }
                }
                CP_COMMIT();
            }
            if (!afload) {
                #pragma unroll
                for (int mt = 0; mt < 2; mt++)
                    ldsm_x4(af[mt][0], af[mt][1], af[mt][2], af[mt][3],
                            a_base + offA[mt]);
                afload = true;
            }
            compute_tile(pg * 2, ti, tj0 + jp, sym);
            if (jp + 1 < len)
                compute_tile(pg * 2 + 1, ti, tj0 + jp + 1, sym);
        }
    }

    // ================= Phase 3: reduce + finalize =================
    #pragma unroll
    for (int o = 16; o; o >>= 1) s += __shfl_xor_sync(0xffffffffu, s, o);
    if (lane == 0) sm.red[wid] = s;
    __syncthreads();
    if (tid == 0) {
        float tot = 0.0f;
        #pragma unroll
        for (int i2 = 0; i2 < 8; i2++) tot += sm.red[i2];
        g_partials[blockIdx.x] = tot;
        __threadfence();
        unsigned int old = atomicAdd(&g_done, 1u);
        sm.lastflag = (old == WORKERS - 1) ? 1u : 0u;
    }
    __syncthreads();
    if (sm.lastflag) {
        __threadfence();
        float v = 0.0f;
        for (int i = tid; i < WORKERS; i += 256) v += g_partials[i];
        #pragma unroll
        for (int o = 16; o; o >>= 1) v += __shfl_xor_sync(0xffffffffu, v, o);
        if (lane == 0) sm.red[wid] = v;
        __syncthreads();
        if (tid == 0) {
            float tot = 0.0f;
            #pragma unroll
            for (int i2 = 0; i2 < 8; i2++) tot += sm.red[i2];
            out[0] = tot * (float)(1.0 / (8.0 * 3844.0 * 3844.0));
            g_bar1 = 0u;
            g_ticket = 0u;
            __threadfence();
            g_done = 0u;
        }
    }
}

extern "C" void kernel_launch(void* const* d_in, const int* in_sizes, int n_in,
                              void* d_out, int out_size) {
    const float* x = (const float*)d_in[0];
    const float* y = (const float*)d_in[1];
    mmd_fused<<<WORKERS, 256>>>(x, y, (float*)d_out);
}

// round 11
// speedup vs baseline: 1.0630x; 1.0630x over previous
#include <cuda_runtime.h>
#include <cuda_bf16.h>
#include <cstdint>

// GlobalPoolDistance: patch-RBF MMD, single fused persistent kernel (R11).
// bf16 mma.sync m16n8k16 computes the exp2 argument directly:
//   A row i = [C2*a_0..C2*a_26, 1, -u_i, 0..]   (u = ||a||^2 * log2e/SIG2)
//   B row j = [b_0..b_26,      -v_j, 1, 0..]
//   acc(i,j) = C2*<a,b> - u - v = -log2e*||a-b||^2/SIG2 ; K = exp2(acc).
// R11: operands staged as PRE-BUILT MMA FRAGMENTS (fragment-major) in global
// memory. Hot loop has NO smem tiles, NO ldmatrix, NO cp.async and NO
// __syncthreads: each warp streams B fragments via double-buffered LDG.128
// and runs fully independently (static chunk round-robin, no ticket).
// Epilogue skip threshold -30 (deterministic bound, see R7); straddle tiles
// force the epilogue; exact diagonals replaced by 1.0.

#define TILE 128
#define BTILE 64
#define NPATCH 3844
#define NROWS 3968
#define NGRP 124                                   // NROWS / 32
#define BATCH 8
#define XY_CHUNKS 1984
#define SYM_CHUNKS_PER 136
#define CHUNKS (XY_CHUNKS + 16 * SYM_CHUNKS_PER)   // 4160
#define WORKERS 296                                // 148 SMs x 2 CTAs
#define STAGE_TASKS (2 * BATCH * NROWS)            // 63488

// fragment-major stages:
//   g_bfrag[img][b][grp][nt][lane] : lane uint4 = {b0kk0, b1kk0, b0kk1, b1kk1}
//   g_afrag[img][b][grp][mt][kk][lane] : lane uint4 = {a0, a1, a2, a3}
__device__ uint4 g_bfrag[2 * BATCH * NGRP * 4 * 32];       // ~4 MB
__device__ uint4 g_afrag[2 * BATCH * NGRP * 2 * 2 * 32];   // ~2 MB
__device__ float g_partials[WORKERS];
__device__ unsigned int g_bar1;
__device__ unsigned int g_done;

__device__ __forceinline__ uint32_t pk(float a, float b) {
    __nv_bfloat162 h = __floats2bfloat162_rn(a, b);
    return *reinterpret_cast<uint32_t*>(&h);
}
__device__ __forceinline__ void mma4(float* d, uint4 a, uint32_t b0, uint32_t b1) {
    asm volatile("mma.sync.aligned.m16n8k16.row.col.f32.bf16.bf16.f32 "
                 "{%0,%1,%2,%3}, {%4,%5,%6,%7}, {%8,%9}, {%0,%1,%2,%3};"
                 : "+f"(d[0]), "+f"(d[1]), "+f"(d[2]), "+f"(d[3])
                 : "r"(a.x), "r"(a.y), "r"(a.z), "r"(a.w), "r"(b0), "r"(b1));
}

__global__ void __launch_bounds__(256, 2)
mmd_fused(const float* __restrict__ x, const float* __restrict__ y,
          float* __restrict__ out) {
    __shared__ float red[8];
    __shared__ unsigned int lastflag;
    const int tid = threadIdx.x;
    const int wid = tid >> 5;
    const int lane = tid & 31;

    const float K1f = 4.9479492581208223f;         // log2e / 0.2916
    const float C2f = 9.8958985162416446f;         // 2*log2e / 0.2916

    // ================= Phase 1: stage MMA fragments =================
    {
        int gtid = blockIdx.x * 256 + tid;
        if (gtid < STAGE_TASKS) {
            int n = gtid % NROWS;
            int t2 = gtid / NROWS;
            int b = t2 & 7;
            int img = t2 >> 3;
            const float* im = img ? y : x;

            float rv[27];
            float u = 0.0f;
            bool valid = (n < NPATCH);
            if (valid) {
                int i = n / 62;
                int j = n - i * 62;
                const float* p = im + b * 12288 + (i << 6) + j;
                float sq = 0.0f;
                #pragma unroll
                for (int c = 0; c < 3; c++)
                    #pragma unroll
                    for (int rr = 0; rr < 3; rr++)
                        #pragma unroll
                        for (int ss = 0; ss < 3; ss++) {
                            float v = p[c * 4096 + (rr << 6) + ss];
                            sq = fmaf(v, v, sq);
                            rv[c * 9 + rr * 3 + ss] = v;
                        }
                u = sq * K1f;
            } else {
                #pragma unroll
                for (int k = 0; k < 27; k++) rv[k] = 0.0f;
            }
            float nu = valid ? -u : -1e30f;

            int grp = n >> 5, local = n & 31;

            // ---- B-form fragments (raw values; [27]=-u, [28]=1) ----
            {
                float bw[32];
                #pragma unroll
                for (int k = 0; k < 27; k++) bw[k] = rv[k];
                bw[27] = nu; bw[28] = 1.0f; bw[29] = bw[30] = bw[31] = 0.0f;
                int nt = local >> 3, nr = local & 7;
                uint4* bdst = g_bfrag +
                    ((((size_t)img * BATCH + b) * NGRP + grp) * 4 + nt) * 32;
                #pragma unroll
                for (int q = 0; q < 4; q++) {
                    uint4 v;
                    v.x = pk(bw[2*q],      bw[2*q+1]);
                    v.y = pk(bw[2*q+8],    bw[2*q+9]);
                    v.z = pk(bw[2*q+16],   bw[2*q+17]);
                    v.w = pk(bw[2*q+24],   bw[2*q+25]);
                    bdst[nr * 4 + q] = v;
                }
            }
            // ---- A-form fragments (C2-scaled; [27]=1, [28]=-u) ----
            {
                float aw[32];
                #pragma unroll
                for (int k = 0; k < 27; k++) aw[k] = C2f * rv[k];
                aw[27] = 1.0f; aw[28] = nu; aw[29] = aw[30] = aw[31] = 0.0f;
                int mt = local >> 4, rr = local & 15;
                uint32_t* adst = reinterpret_cast<uint32_t*>(g_afrag +
                    ((((size_t)img * BATCH + b) * NGRP + grp) * 2 + mt) * 2 * 32);
                #pragma unroll
                for (int kk = 0; kk < 2; kk++)
                    #pragma unroll
                    for (int q = 0; q < 4; q++) {
                        int ln = (rr & 7) * 4 + q;
                        uint32_t lo = pk(aw[2*q + 16*kk],     aw[2*q + 1 + 16*kk]);
                        uint32_t hi = pk(aw[2*q + 8 + 16*kk], aw[2*q + 9 + 16*kk]);
                        uint32_t* p4 = adst + (kk * 32 + ln) * 4;
                        if (rr < 8) { p4[0] = lo; p4[2] = hi; }
                        else        { p4[1] = lo; p4[3] = hi; }
                    }
            }
        }
        __threadfence();
        __syncthreads();
        if (tid == 0) {
            atomicAdd(&g_bar1, 1u);
            unsigned int v;
            do {
                asm volatile("ld.acquire.gpu.global.u32 %0, [%1];"
                             : "=r"(v) : "l"(&g_bar1));
                if (v >= WORKERS) break;
                __nanosleep(64);
            } while (true);
        }
        __syncthreads();
        __threadfence();
    }

    // ================= Phase 2: barrier-free persistent loop =================
    const int mg = wid & 3;          // A rows mg*32..+31 of the 128-row tile
    const int ng = wid >> 2;         // B rows ng*32..+31 of the 64-row tile
    float s = 0.0f;

    for (int c = blockIdx.x; c < CHUNKS; c += WORKERS) {
        // ---- decode 8-tile chunk (tiles 128 rows x 64 cols) ----
        int ti, tj0, len, imgA, imgB, b;
        bool sym;
        if (c < XY_CHUNKS) {
            int seg = c >> 3, q = c & 7;
            b = seg / 31; ti = seg - b * 31;
            tj0 = q * 8; len = (q < 7) ? 8 : 6;    // 62 B-tiles per strip
            sym = false; imgA = 0; imgB = 1;
        } else {
            int d = c - XY_CHUNKS;
            int g = d / SYM_CHUNKS_PER;
            int r = d - g * SYM_CHUNKS_PER;
            int kind = g >> 3; b = g & 7;
            int i = 0;
            for (;;) {
                int cpr = (2 * i + 9) >> 3;        // ceil((2i+2)/8)
                if (r < cpr) break;
                r -= cpr; i++;
            }
            ti = i; tj0 = r * 8;
            len = min(8, 2 * i + 2 - tj0);
            sym = true; imgA = kind; imgB = kind;
        }

        // ---- A fragments for this warp's 32-row slice (register-resident) ----
        const uint4* ap = g_afrag +
            ((((size_t)imgA * BATCH + b) * NGRP + (ti * 4 + mg)) * 2) * 2 * 32;
        uint4 a00 = ap[lane];            // mt0 kk0
        uint4 a01 = ap[32 + lane];       // mt0 kk1
        uint4 a10 = ap[64 + lane];       // mt1 kk0
        uint4 a11 = ap[96 + lane];       // mt1 kk1

        const uint4* bp0 = g_bfrag + (((size_t)imgB * BATCH + b) * NGRP) * 4 * 32;

        auto loadB = [&](uint4* bf, int tj) {
            const uint4* p = bp0 + (size_t)(tj * 2 + ng) * 128;
            bf[0] = p[lane];
            bf[1] = p[32 + lane];
            bf[2] = p[64 + lane];
            bf[3] = p[96 + lane];
        };

        auto compute = [&](const uint4* bf, int tj) {
            float acc[2][4][4];
            #pragma unroll
            for (int mt = 0; mt < 2; mt++)
                #pragma unroll
                for (int nt = 0; nt < 4; nt++)
                    #pragma unroll
                    for (int r = 0; r < 4; r++) acc[mt][nt][r] = 0.0f;

            #pragma unroll
            for (int nt = 0; nt < 4; nt++) {
                mma4(acc[0][nt], a00, bf[nt].x, bf[nt].y);
                mma4(acc[0][nt], a01, bf[nt].z, bf[nt].w);
                mma4(acc[1][nt], a10, bf[nt].x, bf[nt].y);
                mma4(acc[1][nt], a11, bf[nt].z, bf[nt].w);
            }

            bool diagTile = sym && ((tj >> 1) == ti);

            float t8[8];
            #pragma unroll
            for (int mt = 0; mt < 2; mt++)
                #pragma unroll
                for (int nt = 0; nt < 4; nt++)
                    t8[mt * 4 + nt] = fmaxf(fmaxf(acc[mt][nt][0], acc[mt][nt][1]),
                                            fmaxf(acc[mt][nt][2], acc[mt][nt][3]));
            #pragma unroll
            for (int st = 4; st > 0; st >>= 1)
                #pragma unroll
                for (int i2 = 0; i2 < 4; i2++)
                    if (i2 < st) t8[i2] = fmaxf(t8[i2], t8[i2 + st]);

            if (diagTile || __any_sync(0xffffffffu, t8[0] > -30.0f)) {
                float w = sym ? ((tj < 2 * ti) ? 2.0f : 1.0f) : -2.0f;
                int rbase = mg * 32 + (lane >> 2);
                int cbase = ng * 32 + ((lane & 3) << 1);
                int dshift = (tj & 1) << 6;
                float ts = 0.0f;
                #pragma unroll
                for (int mt = 0; mt < 2; mt++)
                    #pragma unroll
                    for (int nt = 0; nt < 4; nt++)
                        #pragma unroll
                        for (int r = 0; r < 4; r++) {
                            int rl = rbase + mt * 16 + ((r >> 1) << 3);
                            int cl = cbase + nt * 8 + (r & 1);
                            bool isd = diagTile && (rl == dshift + cl) &&
                                       (ti * TILE + rl < NPATCH);
                            float e;
                            asm("ex2.approx.ftz.f32 %0, %1;" : "=f"(e)
                                : "f"(acc[mt][nt][r]));
                            ts += isd ? 1.0f : e;
                        }
                s = fmaf(w, ts, s);
            }
        };

        // ---- register double-buffered tile stream (no barriers) ----
        uint4 bA[4], bB[4];
        loadB(bA, tj0);
        int j = 0;
        for (;;) {
            if (j + 1 < len) loadB(bB, tj0 + j + 1);
            compute(bA, tj0 + j);
            if (++j >= len) break;
            if (j + 1 < len) loadB(bA, tj0 + j + 1);
            compute(bB, tj0 + j);
            if (++j >= len) break;
        }
    }

    // ================= Phase 3: reduce + finalize =================
    #pragma unroll
    for (int o = 16; o; o >>= 1) s += __shfl_xor_sync(0xffffffffu, s, o);
    if (lane == 0) red[wid] = s;
    __syncthreads();
    if (tid == 0) {
        float tot = 0.0f;
        #pragma unroll
        for (int i2 = 0; i2 < 8; i2++) tot += red[i2];
        g_partials[blockIdx.x] = tot;
        __threadfence();
        unsigned int old = atomicAdd(&g_done, 1u);
        lastflag = (old == WORKERS - 1) ? 1u : 0u;
    }
    __syncthreads();
    if (lastflag) {
        __threadfence();
        float v = 0.0f;
        for (int i = tid; i < WORKERS; i += 256) v += g_partials[i];
        #pragma unroll
        for (int o = 16; o; o >>= 1) v += __shfl_xor_sync(0xffffffffu, v, o);
        if (lane == 0) red[wid] = v;
        __syncthreads();
        if (tid == 0) {
            float tot = 0.0f;
            #pragma unroll
            for (int i2 = 0; i2 < 8; i2++) tot += red[i2];
            out[0] = tot * (float)(1.0 / (8.0 * 3844.0 * 3844.0));
            g_bar1 = 0u;
            __threadfence();
            g_done = 0u;
        }
    }
}

extern "C" void kernel_launch(void* const* d_in, const int* in_sizes, int n_in,
                              void* d_out, int out_size) {
    const float* x = (const float*)d_in[0];
    const float* y = (const float*)d_in[1];
    mmd_fused<<<WORKERS, 256>>>(x, y, (float*)d_out);
}

// round 12
// speedup vs baseline: 1.1699x; 1.1005x over previous
#include <cuda_runtime.h>
#include <cuda_fp16.h>
#include <cstdint>

// GlobalPoolDistance: patch-RBF MMD, single fused persistent kernel (R12).
// f16 mma.sync m16n8k16 (f16 accumulate) computes the exp2 argument directly:
//   A row i = [C2*a_0..C2*a_26, 1, -u_i, 0..]   (u = ||a||^2 * log2e/SIG2)
//   B row j = [b_0..b_26,      -v_j, 1, 0..]
//   acc(i,j) = C2*<a,b> - u - v = -log2e*||a-b||^2/SIG2 ; K = exp2(acc).
// fp16 (11-bit mantissa > bf16's 8) holds args (~-267) exactly enough; the
// -30 skip threshold has ~200 margin; diagonal tiles FORCE the epilogue and
// diagonals are positionally replaced by exact 1.0. Pads use -60000 (fp16
// range): pad args <= -59k, double-pad overflow -> -inf -> exp2 -> 0.
// Structure = R8 (best): 128x128 tiles, smem + ldmatrix, 4-slot B ring,
// pair processing, 8-tile work-steal chunks, 2 CTAs/SM.

#define TILE 128
#define NPATCH 3844
#define NTILES 31
#define NROWS (NTILES * TILE)                     // 3968
#define BATCH 8
#define ROW_U4 4                                  // 64 B per staged row (32 f16)
#define STAGE_U4 (4 * BATCH * NROWS * ROW_U4)
#define CHUNKS 2208                               // 992 xy + 1216 sym
#define WORKERS 296
#define STAGE_TASKS (2 * BATCH * NROWS)           // 63488

__device__ uint4 g_stage[STAGE_U4];
__device__ float g_partials[WORKERS];
__device__ unsigned int g_bar1;
__device__ unsigned int g_ticket;
__device__ unsigned int g_done;

__device__ __forceinline__ uint32_t smem_to_u32(const void* p) {
    uint32_t a;
    asm("{ .reg .u64 t; cvta.to.shared.u64 t, %1; cvt.u32.u64 %0, t; }"
        : "=r"(a) : "l"(p));
    return a;
}
__device__ __forceinline__ void cp_async16(uint32_t smem, const void* gptr) {
    asm volatile("cp.async.cg.shared.global [%0], [%1], 16;"
                 :: "r"(smem), "l"(gptr) : "memory");
}
#define CP_COMMIT() asm volatile("cp.async.commit_group;" ::: "memory")
#define CP_WAIT0()  asm volatile("cp.async.wait_group 0;" ::: "memory")

__device__ __forceinline__ void ldsm_x4(uint32_t& r0, uint32_t& r1,
                                        uint32_t& r2, uint32_t& r3, uint32_t a) {
    asm volatile("ldmatrix.sync.aligned.m8n8.x4.shared.b16 {%0,%1,%2,%3}, [%4];"
                 : "=r"(r0), "=r"(r1), "=r"(r2), "=r"(r3) : "r"(a));
}
// f16 MMA with f16 accumulate: C fragment = 2 packed f16x2 regs.
__device__ __forceinline__ void mma_h(uint32_t* d, const uint32_t* a,
                                      uint32_t b0, uint32_t b1) {
    asm volatile("mma.sync.aligned.m16n8k16.row.col.f16.f16.f16.f16 "
                 "{%0,%1}, {%2,%3,%4,%5}, {%6,%7}, {%0,%1};"
                 : "+r"(d[0]), "+r"(d[1])
                 : "r"(a[0]), "r"(a[1]), "r"(a[2]), "r"(a[3]), "r"(b0), "r"(b1));
}
__device__ __forceinline__ uint32_t pkh(float a, float b) {
    __half2 h = __floats2half2_rn(a, b);
    return *reinterpret_cast<uint32_t*>(&h);
}
__device__ __forceinline__ uint32_t hmax2u(uint32_t a, uint32_t b) {
    __half2 r = __hmax2(*reinterpret_cast<__half2*>(&a),
                        *reinterpret_cast<__half2*>(&b));
    return *reinterpret_cast<uint32_t*>(&r);
}

struct __align__(1024) Smem {
    uint4 A[512];          // 8 KB A tile (128 rows x 64 B)
    uint4 B[4][512];       // 4-slot B ring, 8 KB each
    float red[8];
    unsigned int ticket;
    unsigned int lastflag;
};

__global__ void __launch_bounds__(256, 2)
mmd_fused(const float* __restrict__ x, const float* __restrict__ y,
          float* __restrict__ out) {
    __shared__ Smem sm;
    const int tid = threadIdx.x;
    const int wid = tid >> 5;
    const int lane = tid & 31;

    const float K1f = 4.9479492581208223f;        // log2e / 0.2916
    const float C2f = 9.8958985162416446f;        // 2*log2e / 0.2916

    // ================= Phase 1: stage f16 operand rows =================
    {
        int gtid = blockIdx.x * 256 + tid;
        if (gtid < STAGE_TASKS) {
            int n = gtid % NROWS;
            int t2 = gtid / NROWS;
            int b = t2 & 7;
            int img = t2 >> 3;
            const float* im = img ? y : x;

            float rv[27];
            float u = 0.0f;
            bool valid = (n < NPATCH);
            if (valid) {
                int i = n / 62;
                int j = n - i * 62;
                const float* p = im + b * 12288 + (i << 6) + j;
                float sq = 0.0f;
                #pragma unroll
                for (int c = 0; c < 3; c++)
                    #pragma unroll
                    for (int rr = 0; rr < 3; rr++)
                        #pragma unroll
                        for (int ss = 0; ss < 3; ss++) {
                            float v = p[c * 4096 + (rr << 6) + ss];
                            sq = fmaf(v, v, sq);
                            rv[c * 9 + rr * 3 + ss] = v;
                        }
                u = sq * K1f;
            } else {
                #pragma unroll
                for (int k = 0; k < 27; k++) rv[k] = 0.0f;
            }
            uint32_t sw = (uint32_t)(n >> 1) & 3u;

            #pragma unroll
            for (int form = 0; form < 2; form++) {
                float rowv[32];
                #pragma unroll
                for (int k = 0; k < 27; k++)
                    rowv[k] = form ? rv[k] : (C2f * rv[k]);
                float nu = valid ? -u : -60000.0f;   // fp16-range pad sentinel
                if (form) { rowv[27] = nu;   rowv[28] = 1.0f; }
                else      { rowv[27] = 1.0f; rowv[28] = nu;   }
                rowv[29] = rowv[30] = rowv[31] = 0.0f;
                uint32_t wds[16];
                #pragma unroll
                for (int q = 0; q < 16; q++)
                    wds[q] = pkh(rowv[2*q], rowv[2*q+1]);
                int ver = form * 2 + img;
                int base = ((ver * BATCH + b) * NROWS + n) * ROW_U4;
                #pragma unroll
                for (int c = 0; c < 4; c++)
                    g_stage[base + (c ^ sw)] =
                        make_uint4(wds[4*c], wds[4*c+1], wds[4*c+2], wds[4*c+3]);
            }
        }
        __threadfence();
        __syncthreads();
        if (tid == 0) {
            atomicAdd(&g_bar1, 1u);
            unsigned int v;
            do {
                asm volatile("ld.acquire.gpu.global.u32 %0, [%1];"
                             : "=r"(v) : "l"(&g_bar1));
                if (v >= WORKERS) break;
                __nanosleep(64);
            } while (true);
        }
        __syncthreads();
        __threadfence();
    }

    // ================= Phase 2: persistent tile loop =================
    const int mg = wid & 3;          // A rows mg*32..+31
    const int ng = wid >> 2;         // B rows ng*64..+63
    const uint32_t a_base = smem_to_u32(sm.A);
    const uint32_t b_ring = smem_to_u32(sm.B);    // 4 slots x 8192 B

    uint32_t offA[2][2];
    #pragma unroll
    for (int mt = 0; mt < 2; mt++)
        #pragma unroll
        for (int k = 0; k < 2; k++) {
            int rowA = mg * 32 + mt * 16 + (lane & 15);
            int ch = k * 2 + (lane >> 4);
            int swz = ch ^ ((rowA >> 1) & 3);
            offA[mt][k] = (uint32_t)(rowA * 64 + swz * 16);
        }
    uint32_t offB[2];
    #pragma unroll
    for (int k = 0; k < 2; k++) {
        int rloc = (lane & 7) + ((lane >> 4) << 3);
        int rowB = ng * 64 + rloc;
        int ch = k * 2 + ((lane >> 3) & 1);
        int swz = ch ^ ((rowB >> 1) & 3);
        offB[k] = (uint32_t)(rowB * 64 + swz * 16);
    }

    float s = 0.0f;
    uint32_t af[2][2][4];

    const uint32_t NEGINF30 = pkh(-30.0f, -30.0f);  // threshold as packed f16

    auto compute_tile = [&](int slot, int ti, int tj, bool sym) {
        const uint32_t bb = b_ring + (uint32_t)(slot * 8192);
        uint32_t acc[2][8][2];                      // packed f16x2 accumulators
        #pragma unroll
        for (int mt = 0; mt < 2; mt++)
            #pragma unroll
            for (int nt = 0; nt < 8; nt++)
                acc[mt][nt][0] = acc[mt][nt][1] = 0u;

        #pragma unroll
        for (int k = 0; k < 2; k++)
            #pragma unroll
            for (int p = 0; p < 4; p++) {
                uint32_t b0, b1, b2, b3;
                ldsm_x4(b0, b1, b2, b3, bb + offB[k] + (uint32_t)(p * 1024));
                mma_h(acc[0][2*p],   af[0][k], b0, b1);
                mma_h(acc[0][2*p+1], af[0][k], b2, b3);
                mma_h(acc[1][2*p],   af[1][k], b0, b1);
                mma_h(acc[1][2*p+1], af[1][k], b2, b3);
            }

        bool diagTile = sym && (tj == ti);

        // packed max tree over 32 f16x2 regs (64 args)
        uint32_t m16[16];
        #pragma unroll
        for (int mt = 0; mt < 2; mt++)
            #pragma unroll
            for (int nt = 0; nt < 8; nt++)
                m16[mt * 8 + nt] = hmax2u(acc[mt][nt][0], acc[mt][nt][1]);
        #pragma unroll
        for (int st = 8; st > 0; st >>= 1)
            #pragma unroll
            for (int i2 = 0; i2 < 8; i2++)
                if (i2 < st) m16[i2] = hmax2u(m16[i2], m16[i2 + st]);
        __half2 hm = *reinterpret_cast<__half2*>(&m16[0]);
        float mx = fmaxf(__low2float(hm), __high2float(hm));

        if (diagTile || __any_sync(0xffffffffu, mx > -30.0f)) {
            float w = sym ? ((tj == ti) ? 1.0f : 2.0f) : -2.0f;
            int rbase = mg * 32 + (lane >> 2);
            int cbase = ng * 64 + ((lane & 3) << 1);
            float ts = 0.0f;
            #pragma unroll
            for (int mt = 0; mt < 2; mt++)
                #pragma unroll
                for (int nt = 0; nt < 8; nt++)
                    #pragma unroll
                    for (int r = 0; r < 2; r++) {
                        int rl = rbase + mt * 16 + (r << 3);
                        __half2 hv = *reinterpret_cast<__half2*>(&acc[mt][nt][r]);
                        float a0 = __low2float(hv);
                        float a1 = __high2float(hv);
                        int cl0 = cbase + nt * 8;
                        bool ok = (ti * TILE + rl < NPATCH);
                        bool d0 = diagTile && ok && (rl == cl0);
                        bool d1 = diagTile && ok && (rl == cl0 + 1);
                        float e0, e1;
                        asm("ex2.approx.ftz.f32 %0, %1;" : "=f"(e0) : "f"(a0));
                        asm("ex2.approx.ftz.f32 %0, %1;" : "=f"(e1) : "f"(a1));
                        ts += (d0 ? 1.0f : e0) + (d1 ? 1.0f : e1);
                    }
            s = fmaf(w, ts, s);
        }
    };

    for (;;) {
        __syncthreads();
        if (tid == 0) sm.ticket = atomicAdd(&g_ticket, 1u);
        __syncthreads();
        unsigned int c = sm.ticket;
        if (c >= CHUNKS) break;

        // ---- decode 8-tile chunk (128x128 tiles) ----
        int ti, tj0, len, verA, verB, b;
        bool sym;
        if (c < 992u) {
            int seg = c >> 2, q = c & 3;
            b = seg / 31; ti = seg - b * 31;
            tj0 = q * 8; len = (q < 3) ? 8 : 7;
            sym = false; verA = 0; verB = 3;
        } else {
            int d = (int)c - 992;
            int g = d / 76;
            int r = d - g * 76;
            int kind = g >> 3; b = g & 7;
            if (r < 8)       { ti = r;              tj0 = 0; }
            else if (r < 24) { int q = r - 8;  ti = 8  + (q >> 1); tj0 = (q & 1) * 8; }
            else if (r < 48) { int q = r - 24; int qd = q / 3; ti = 16 + qd; tj0 = (q - qd * 3) * 8; }
            else             { int q = r - 48; ti = 24 + (q >> 2); tj0 = (q & 3) * 8; }
            len = min(8, ti + 1 - tj0);
            sym = true; verA = kind; verB = 2 + kind;
        }

        const uint4* bbase = g_stage + ((verB * BATCH + b) * NROWS) * ROW_U4;

        {
            const uint4* asrc = g_stage + ((verA * BATCH + b) * NROWS + ti * TILE) * ROW_U4;
            cp_async16(a_base + (uint32_t)(tid * 16), asrc + tid);
            cp_async16(a_base + (uint32_t)((tid + 256) * 16), asrc + tid + 256);
            const uint4* b0src = bbase + (tj0 * TILE) * ROW_U4;
            cp_async16(b_ring + (uint32_t)(tid * 16), b0src + tid);
            cp_async16(b_ring + (uint32_t)((tid + 256) * 16), b0src + tid + 256);
            if (len > 1) {
                const uint4* b1src = bbase + ((tj0 + 1) * TILE) * ROW_U4;
                cp_async16(b_ring + (uint32_t)(8192 + tid * 16), b1src + tid);
                cp_async16(b_ring + (uint32_t)(8192 + (tid + 256) * 16), b1src + tid + 256);
            }
            CP_COMMIT();
        }

        bool afload = false;
        for (int jp = 0; jp < len; jp += 2) {
            CP_WAIT0();
            __syncthreads();
            int pg = (jp >> 1) & 1;
            if (jp + 2 < len) {
                int og = pg ^ 1;
                uint32_t nb = b_ring + (uint32_t)(og * 2 * 8192);
                const uint4* bs = bbase + ((tj0 + jp + 2) * TILE) * ROW_U4;
                cp_async16(nb + (uint32_t)(tid * 16), bs + tid);
                cp_async16(nb + (uint32_t)((tid + 256) * 16), bs + tid + 256);
                if (jp + 3 < len) {
                    const uint4* bs2 = bbase + ((tj0 + jp + 3) * TILE) * ROW_U4;
                    cp_async16(nb + (uint32_t)(8192 + tid * 16), bs2 + tid);
                    cp_async16(nb + (uint32_t)(8192 + (tid + 256) * 16), bs2 + tid + 256);
                }
                CP_COMMIT();
            }
            if (!afload) {
                #pragma unroll
                for (int mt = 0; mt < 2; mt++)
                    #pragma unroll
                    for (int k = 0; k < 2; k++)
                        ldsm_x4(af[mt][k][0], af[mt][k][1], af[mt][k][2], af[mt][k][3],
                                a_base + offA[mt][k]);
                afload = true;
            }
            compute_tile(pg * 2, ti, tj0 + jp, sym);
            if (jp + 1 < len)
                compute_tile(pg * 2 + 1, ti, tj0 + jp + 1, sym);
        }
    }

    // ================= Phase 3: reduce + finalize =================
    #pragma unroll
    for (int o = 16; o; o >>= 1) s += __shfl_xor_sync(0xffffffffu, s, o);
    if (lane == 0) sm.red[wid] = s;
    __syncthreads();
    if (tid == 0) {
        float tot = 0.0f;
        #pragma unroll
        for (int i2 = 0; i2 < 8; i2++) tot += sm.red[i2];
        g_partials[blockIdx.x] = tot;
        __threadfence();
        unsigned int old = atomicAdd(&g_done, 1u);
        sm.lastflag = (old == WORKERS - 1) ? 1u : 0u;
    }
    __syncthreads();
    if (sm.lastflag) {
        __threadfence();
        float v = 0.0f;
        for (int i = tid; i < WORKERS; i += 256) v += g_partials[i];
        #pragma unroll
        for (int o = 16; o; o >>= 1) v += __shfl_xor_sync(0xffffffffu, v, o);
        if (lane == 0) sm.red[wid] = v;
        __syncthreads();
        if (tid == 0) {
            float tot = 0.0f;
            #pragma unroll
            for (int i2 = 0; i2 < 8; i2++) tot += sm.red[i2];
            out[0] = tot * (float)(1.0 / (8.0 * 3844.0 * 3844.0));
            g_bar1 = 0u;
            g_ticket = 0u;
            __threadfence();
            g_done = 0u;
        }
    }
}

extern "C" void kernel_launch(void* const* d_in, const int* in_sizes, int n_in,
                              void* d_out, int out_size) {
    const float* x = (const float*)d_in[0];
    const float* y = (const float*)d_in[1];
    mmd_fused<<<WORKERS, 256>>>(x, y, (float*)d_out);
}

// round 13
// speedup vs baseline: 1.1724x; 1.0022x over previous
#include <cuda_runtime.h>
#include <cuda_fp16.h>
#include <cstdint>

// GlobalPoolDistance: patch-RBF MMD, single fused persistent kernel (R13).
// f16 mma.sync m16n8k16 (f16 accumulate) computes the exp2 argument directly:
//   A row i = [C2*a_0..C2*a_26, 1, -u_i, 0..]   (u = ||a||^2 * log2e/SIG2)
//   B row j = [b_0..b_26,      -v_j, 1, 0..]
//   acc(i,j) = C2*<a,b> - u - v = -log2e*||a-b||^2/SIG2 ; K = exp2(acc).
// Epilogue skip threshold -30 (deterministic per-term bound, see R7);
// diagonal tiles force the epilogue; diagonals replaced by exact 1.0.
// R13: 8-slot B ring in DYNAMIC smem (72 KB), 4-tile barrier windows
// (3 syncs per 8-tile chunk instead of 6), straight-line 4-tile bodies so
// ptxas overlaps guard tails with the next tile's LDSM/MMA.

#define TILE 128
#define NPATCH 3844
#define NTILES 31
#define NROWS (NTILES * TILE)                     // 3968
#define BATCH 8
#define ROW_U4 4                                  // 64 B per staged row (32 f16)
#define STAGE_U4 (4 * BATCH * NROWS * ROW_U4)
#define CHUNKS 2208                               // 992 xy + 1216 sym
#define WORKERS 296
#define STAGE_TASKS (2 * BATCH * NROWS)           // 63488

// dynamic smem layout
#define SMEM_A_OFF   0                            // 8 KB A tile
#define SMEM_B_OFF   8192                         // 8 slots x 8 KB
#define SMEM_RED_OFF (8192 + 8 * 8192)            // 73728
#define SMEM_TKT_OFF (SMEM_RED_OFF + 32)
#define SMEM_LST_OFF (SMEM_TKT_OFF + 4)
#define SMEM_BYTES   (SMEM_LST_OFF + 4 + 24)      // 73768 -> 73792

__device__ uint4 g_stage[STAGE_U4];
__device__ float g_partials[WORKERS];
__device__ unsigned int g_bar1;
__device__ unsigned int g_ticket;
__device__ unsigned int g_done;

__device__ __forceinline__ uint32_t smem_to_u32(const void* p) {
    uint32_t a;
    asm("{ .reg .u64 t; cvta.to.shared.u64 t, %1; cvt.u32.u64 %0, t; }"
        : "=r"(a) : "l"(p));
    return a;
}
__device__ __forceinline__ void cp_async16(uint32_t smem, const void* gptr) {
    asm volatile("cp.async.cg.shared.global [%0], [%1], 16;"
                 :: "r"(smem), "l"(gptr) : "memory");
}
#define CP_COMMIT() asm volatile("cp.async.commit_group;" ::: "memory")
#define CP_WAIT0()  asm volatile("cp.async.wait_group 0;" ::: "memory")

__device__ __forceinline__ void ldsm_x4(uint32_t& r0, uint32_t& r1,
                                        uint32_t& r2, uint32_t& r3, uint32_t a) {
    asm volatile("ldmatrix.sync.aligned.m8n8.x4.shared.b16 {%0,%1,%2,%3}, [%4];"
                 : "=r"(r0), "=r"(r1), "=r"(r2), "=r"(r3) : "r"(a));
}
// f16 MMA with f16 accumulate: C fragment = 2 packed f16x2 regs.
__device__ __forceinline__ void mma_h(uint32_t* d, const uint32_t* a,
                                      uint32_t b0, uint32_t b1) {
    asm volatile("mma.sync.aligned.m16n8k16.row.col.f16.f16.f16.f16 "
                 "{%0,%1}, {%2,%3,%4,%5}, {%6,%7}, {%0,%1};"
                 : "+r"(d[0]), "+r"(d[1])
                 : "r"(a[0]), "r"(a[1]), "r"(a[2]), "r"(a[3]), "r"(b0), "r"(b1));
}
__device__ __forceinline__ uint32_t pkh(float a, float b) {
    __half2 h = __floats2half2_rn(a, b);
    return *reinterpret_cast<uint32_t*>(&h);
}
__device__ __forceinline__ uint32_t hmax2u(uint32_t a, uint32_t b) {
    __half2 r = __hmax2(*reinterpret_cast<__half2*>(&a),
                        *reinterpret_cast<__half2*>(&b));
    return *reinterpret_cast<uint32_t*>(&r);
}

extern __shared__ __align__(1024) char dsm[];

__global__ void __launch_bounds__(256, 2)
mmd_fused(const float* __restrict__ x, const float* __restrict__ y,
          float* __restrict__ out) {
    const int tid = threadIdx.x;
    const int wid = tid >> 5;
    const int lane = tid & 31;

    float* red = reinterpret_cast<float*>(dsm + SMEM_RED_OFF);
    unsigned int* tkt = reinterpret_cast<unsigned int*>(dsm + SMEM_TKT_OFF);
    unsigned int* lst = reinterpret_cast<unsigned int*>(dsm + SMEM_LST_OFF);

    const float K1f = 4.9479492581208223f;        // log2e / 0.2916
    const float C2f = 9.8958985162416446f;        // 2*log2e / 0.2916

    // ================= Phase 1: stage f16 operand rows =================
    {
        int gtid = blockIdx.x * 256 + tid;
        if (gtid < STAGE_TASKS) {
            int n = gtid % NROWS;
            int t2 = gtid / NROWS;
            int b = t2 & 7;
            int img = t2 >> 3;
            const float* im = img ? y : x;

            float rv[27];
            float u = 0.0f;
            bool valid = (n < NPATCH);
            if (valid) {
                int i = n / 62;
                int j = n - i * 62;
                const float* p = im + b * 12288 + (i << 6) + j;
                float sq = 0.0f;
                #pragma unroll
                for (int c = 0; c < 3; c++)
                    #pragma unroll
                    for (int rr = 0; rr < 3; rr++)
                        #pragma unroll
                        for (int ss = 0; ss < 3; ss++) {
                            float v = p[c * 4096 + (rr << 6) + ss];
                            sq = fmaf(v, v, sq);
                            rv[c * 9 + rr * 3 + ss] = v;
                        }
                u = sq * K1f;
            } else {
                #pragma unroll
                for (int k = 0; k < 27; k++) rv[k] = 0.0f;
            }
            uint32_t sw = (uint32_t)(n >> 1) & 3u;

            #pragma unroll
            for (int form = 0; form < 2; form++) {
                float rowv[32];
                #pragma unroll
                for (int k = 0; k < 27; k++)
                    rowv[k] = form ? rv[k] : (C2f * rv[k]);
                float nu = valid ? -u : -60000.0f;   // fp16-range pad sentinel
                if (form) { rowv[27] = nu;   rowv[28] = 1.0f; }
                else      { rowv[27] = 1.0f; rowv[28] = nu;   }
                rowv[29] = rowv[30] = rowv[31] = 0.0f;
                uint32_t wds[16];
                #pragma unroll
                for (int q = 0; q < 16; q++)
                    wds[q] = pkh(rowv[2*q], rowv[2*q+1]);
                int ver = form * 2 + img;
                int base = ((ver * BATCH + b) * NROWS + n) * ROW_U4;
                #pragma unroll
                for (int c = 0; c < 4; c++)
                    g_stage[base + (c ^ sw)] =
                        make_uint4(wds[4*c], wds[4*c+1], wds[4*c+2], wds[4*c+3]);
            }
        }
        __threadfence();
        __syncthreads();
        if (tid == 0) {
            atomicAdd(&g_bar1, 1u);
            unsigned int v;
            do {
                asm volatile("ld.acquire.gpu.global.u32 %0, [%1];"
                             : "=r"(v) : "l"(&g_bar1));
                if (v >= WORKERS) break;
                __nanosleep(64);
            } while (true);
        }
        __syncthreads();
        __threadfence();
    }

    // ================= Phase 2: persistent tile loop =================
    const int mg = wid & 3;          // A rows mg*32..+31
    const int ng = wid >> 2;         // B rows ng*64..+63
    const uint32_t a_base = smem_to_u32(dsm) + SMEM_A_OFF;
    const uint32_t b_ring = smem_to_u32(dsm) + SMEM_B_OFF;   // 8 x 8192 B

    uint32_t offA[2][2];
    #pragma unroll
    for (int mt = 0; mt < 2; mt++)
        #pragma unroll
        for (int k = 0; k < 2; k++) {
            int rowA = mg * 32 + mt * 16 + (lane & 15);
            int ch = k * 2 + (lane >> 4);
            int swz = ch ^ ((rowA >> 1) & 3);
            offA[mt][k] = (uint32_t)(rowA * 64 + swz * 16);
        }
    uint32_t offB[2];
    #pragma unroll
    for (int k = 0; k < 2; k++) {
        int rloc = (lane & 7) + ((lane >> 4) << 3);
        int rowB = ng * 64 + rloc;
        int ch = k * 2 + ((lane >> 3) & 1);
        int swz = ch ^ ((rowB >> 1) & 3);
        offB[k] = (uint32_t)(rowB * 64 + swz * 16);
    }

    float s = 0.0f;
    uint32_t af[2][2][4];

    auto compute_tile = [&](int slot, int ti, int tj, bool sym) {
        const uint32_t bb = b_ring + (uint32_t)(slot * 8192);
        uint32_t acc[2][8][2];                      // packed f16x2 accumulators
        #pragma unroll
        for (int mt = 0; mt < 2; mt++)
            #pragma unroll
            for (int nt = 0; nt < 8; nt++)
                acc[mt][nt][0] = acc[mt][nt][1] = 0u;

        #pragma unroll
        for (int k = 0; k < 2; k++)
            #pragma unroll
            for (int p = 0; p < 4; p++) {
                uint32_t b0, b1, b2, b3;
                ldsm_x4(b0, b1, b2, b3, bb + offB[k] + (uint32_t)(p * 1024));
                mma_h(acc[0][2*p],   af[0][k], b0, b1);
                mma_h(acc[0][2*p+1], af[0][k], b2, b3);
                mma_h(acc[1][2*p],   af[1][k], b0, b1);
                mma_h(acc[1][2*p+1], af[1][k], b2, b3);
            }

        bool diagTile = sym && (tj == ti);

        // packed max tree over 32 f16x2 regs (64 args)
        uint32_t m16[16];
        #pragma unroll
        for (int mt = 0; mt < 2; mt++)
            #pragma unroll
            for (int nt = 0; nt < 8; nt++)
                m16[mt * 8 + nt] = hmax2u(acc[mt][nt][0], acc[mt][nt][1]);
        #pragma unroll
        for (int st = 8; st > 0; st >>= 1)
            #pragma unroll
            for (int i2 = 0; i2 < 8; i2++)
                if (i2 < st) m16[i2] = hmax2u(m16[i2], m16[i2 + st]);
        __half2 hm = *reinterpret_cast<__half2*>(&m16[0]);
        float mx = fmaxf(__low2float(hm), __high2float(hm));

        if (diagTile || __any_sync(0xffffffffu, mx > -30.0f)) {
            float w = sym ? ((tj == ti) ? 1.0f : 2.0f) : -2.0f;
            int rbase = mg * 32 + (lane >> 2);
            int cbase = ng * 64 + ((lane & 3) << 1);
            float ts = 0.0f;
            #pragma unroll
            for (int mt = 0; mt < 2; mt++)
                #pragma unroll
                for (int nt = 0; nt < 8; nt++)
                    #pragma unroll
                    for (int r = 0; r < 2; r++) {
                        int rl = rbase + mt * 16 + (r << 3);
                        __half2 hv = *reinterpret_cast<__half2*>(&acc[mt][nt][r]);
                        float a0 = __low2float(hv);
                        float a1 = __high2float(hv);
                        int cl0 = cbase + nt * 8;
                        bool ok = (ti * TILE + rl < NPATCH);
                        bool d0 = diagTile && ok && (rl == cl0);
                        bool d1 = diagTile && ok && (rl == cl0 + 1);
                        float e0, e1;
                        asm("ex2.approx.ftz.f32 %0, %1;" : "=f"(e0) : "f"(a0));
                        asm("ex2.approx.ftz.f32 %0, %1;" : "=f"(e1) : "f"(a1));
                        ts += (d0 ? 1.0f : e0) + (d1 ? 1.0f : e1);
                    }
            s = fmaf(w, ts, s);
        }
    };

    // load `cnt` B tiles (tj0b..tj0b+cnt-1) into slots slot0..slot0+cnt-1
    auto loadB = [&](const uint4* bbase, int tj0b, int cnt, int slot0) {
        for (int t = 0; t < cnt; t++) {
            const uint4* bs = bbase + ((tj0b + t) * TILE) * ROW_U4;
            uint32_t dst = b_ring + (uint32_t)((slot0 + t) * 8192);
            cp_async16(dst + (uint32_t)(tid * 16), bs + tid);
            cp_async16(dst + (uint32_t)((tid + 256) * 16), bs + tid + 256);
        }
    };

    for (;;) {
        __syncthreads();
        if (tid == 0) *tkt = atomicAdd(&g_ticket, 1u);
        __syncthreads();
        unsigned int c = *tkt;
        if (c >= CHUNKS) break;

        // ---- decode 8-tile chunk (128x128 tiles) ----
        int ti, tj0, len, verA, verB, b;
        bool sym;
        if (c < 992u) {
            int seg = c >> 2, q = c & 3;
            b = seg / 31; ti = seg - b * 31;
            tj0 = q * 8; len = (q < 3) ? 8 : 7;
            sym = false; verA = 0; verB = 3;
        } else {
            int d = (int)c - 992;
            int g = d / 76;
            int r = d - g * 76;
            int kind = g >> 3; b = g & 7;
            if (r < 8)       { ti = r;              tj0 = 0; }
            else if (r < 24) { int q = r - 8;  ti = 8  + (q >> 1); tj0 = (q & 1) * 8; }
            else if (r < 48) { int q = r - 24; int qd = q / 3; ti = 16 + qd; tj0 = (q - qd * 3) * 8; }
            else             { int q = r - 48; ti = 24 + (q >> 2); tj0 = (q & 3) * 8; }
            len = min(8, ti + 1 - tj0);
            sym = true; verA = kind; verB = 2 + kind;
        }

        const uint4* bbase = g_stage + ((verB * BATCH + b) * NROWS) * ROW_U4;

        // ---- prologue: A + first window (up to 4 B tiles) ----
        {
            const uint4* asrc = g_stage + ((verA * BATCH + b) * NROWS + ti * TILE) * ROW_U4;
            cp_async16(a_base + (uint32_t)(tid * 16), asrc + tid);
            cp_async16(a_base + (uint32_t)((tid + 256) * 16), asrc + tid + 256);
            loadB(bbase, tj0, min(len, 4), 0);
            CP_COMMIT();
        }

        int grp = 0;
        for (int w0 = 0; w0 < len; w0 += 4, grp ^= 1) {
            CP_WAIT0();
            __syncthreads();                 // window data visible; other group free
            int nxt = w0 + 4;
            if (nxt < len) {
                loadB(bbase, tj0 + nxt, min(4, len - nxt), (grp ^ 1) * 4);
                CP_COMMIT();
            }
            if (w0 == 0) {
                #pragma unroll
                for (int mt = 0; mt < 2; mt++)
                    #pragma unroll
                    for (int k = 0; k < 2; k++)
                        ldsm_x4(af[mt][k][0], af[mt][k][1], af[mt][k][2], af[mt][k][3],
                                a_base + offA[mt][k]);
            }
            int s0 = grp * 4;
            int rem = len - w0;
            if (rem >= 4) {                  // straight-line 4 tiles for ILP
                compute_tile(s0,     ti, tj0 + w0,     sym);
                compute_tile(s0 + 1, ti, tj0 + w0 + 1, sym);
                compute_tile(s0 + 2, ti, tj0 + w0 + 2, sym);
                compute_tile(s0 + 3, ti, tj0 + w0 + 3, sym);
            } else {
                for (int t = 0; t < rem; t++)
                    compute_tile(s0 + t, ti, tj0 + w0 + t, sym);
            }
        }
    }

    // ================= Phase 3: reduce + finalize =================
    #pragma unroll
    for (int o = 16; o; o >>= 1) s += __shfl_xor_sync(0xffffffffu, s, o);
    if (lane == 0) red[wid] = s;
    __syncthreads();
    if (tid == 0) {
        float tot = 0.0f;
        #pragma unroll
        for (int i2 = 0; i2 < 8; i2++) tot += red[i2];
        g_partials[blockIdx.x] = tot;
        __threadfence();
        unsigned int old = atomicAdd(&g_done, 1u);
        *lst = (old == WORKERS - 1) ? 1u : 0u;
    }
    __syncthreads();
    if (*lst) {
        __threadfence();
        float v = 0.0f;
        for (int i = tid; i < WORKERS; i += 256) v += g_partials[i];
        #pragma unroll
        for (int o = 16; o; o >>= 1) v += __shfl_xor_sync(0xffffffffu, v, o);
        if (lane == 0) red[wid] = v;
        __syncthreads();
        if (tid == 0) {
            float tot = 0.0f;
            #pragma unroll
            for (int i2 = 0; i2 < 8; i2++) tot += red[i2];
            out[0] = tot * (float)(1.0 / (8.0 * 3844.0 * 3844.0));
            g_bar1 = 0u;
            g_ticket = 0u;
            __threadfence();
            g_done = 0u;
        }
    }
}

extern "C" void kernel_launch(void* const* d_in, const int* in_sizes, int n_in,
                              void* d_out, int out_size) {
    const float* x = (const float*)d_in[0];
    const float* y = (const float*)d_in[1];
    cudaFuncSetAttribute(mmd_fused,
                         cudaFuncAttributeMaxDynamicSharedMemorySize, SMEM_BYTES);
    mmd_fused<<<WORKERS, 256, SMEM_BYTES>>>(x, y, (float*)d_out);
}